// round 8
// baseline (speedup 1.0000x reference)
#include <cuda_runtime.h>
#include <cstdint>

// ---------------------------------------------------------------------------
// Problem constants
// ---------------------------------------------------------------------------
#define L_NUM 2
#define HS    512
#define BB    64
#define SS    1024
#define INW   512
#define ROWS  1024            // 2 gates * HS, interleaved: r = 2*h + g' (g': 0=z, 1=n)
#define NCTA  128             // persistent step CTAs (1/SM, co-resident)
#define SEQ_ELEMS (BB*SS*HS)

// ---------------------------------------------------------------------------
// Device scratch
// ---------------------------------------------------------------------------
__device__ __align__(16) float g_WG  [L_NUM*ROWS*INW];             // 4 MB [l][r][i], tf32-rounded
__device__ __align__(16) float g_UG  [L_NUM*ROWS*HS];              // 4 MB [l][r][o], tf32-rounded
__device__ __align__(16) float g_bias[L_NUM*ROWS];
__device__ __align__(16) float g_xr  [(size_t)BB*SS*INW];          // 128 MB tf32-rounded x
__device__ __align__(16) float g_Gx  [(size_t)SS*L_NUM*BB*ROWS];   // 512 MB [t][l][b][r]
__device__ __align__(16) float g_Hbuf[2*L_NUM*HS*BB];              // ping-pong [p][l][h][b]
__device__ unsigned long long g_arrive;

__device__ __forceinline__ float rna_tf32(float x) {
    uint32_t r;
    asm("cvt.rna.tf32.f32 %0, %1;" : "=r"(r) : "f"(x));
    return __uint_as_float(r);
}

// D (4xf32) += A (m16k8 tf32) * B (k8n8 tf32), accumulate in place
__device__ __forceinline__ void mma_tf32(float* d, const uint32_t* a, const uint32_t* bf) {
    asm volatile(
        "mma.sync.aligned.m16n8k8.row.col.f32.tf32.tf32.f32 "
        "{%0,%1,%2,%3}, {%4,%5,%6,%7}, {%8,%9}, {%0,%1,%2,%3};"
        : "+f"(d[0]), "+f"(d[1]), "+f"(d[2]), "+f"(d[3])
        : "r"(a[0]), "r"(a[1]), "r"(a[2]), "r"(a[3]), "r"(bf[0]), "r"(bf[1]));
}

// ---------------------------------------------------------------------------
// Kernel A: combined weights (tf32-rounded) + biases
// ---------------------------------------------------------------------------
__global__ void combine_kernel(const float* __restrict__ W1, const float* __restrict__ W2,
                               const float* __restrict__ U1, const float* __restrict__ U2,
                               const float* __restrict__ dW1, const float* __restrict__ dW2,
                               const float* __restrict__ dU1, const float* __restrict__ dU2,
                               const float* __restrict__ b1, const float* __restrict__ b2)
{
    int idx = blockIdx.x * blockDim.x + threadIdx.x;   // L*ROWS*INW threads
    int l   = idx >> 19;
    int rem = idx & 524287;
    int r   = rem >> 9;
    int i   = rem & 511;
    int h   = r >> 1;
    int g   = (r & 1) + 1;                             // original gate (1=z, 2=n)

    float w1  = W1 [l*3 + g];
    float dw1 = dW1[l*3 + g];
    float u1  = U1 [l*3 + g];
    float du1 = dU1[l*3 + g];
    int src = (l*HS + h)*INW + i;
    g_WG[idx] = rna_tf32(w1*W2[src] + dw1*dW2[src]);
    g_UG[idx] = rna_tf32(u1*U2[src] + du1*dU2[src]);

    if (idx < L_NUM*ROWS) {
        int ll = idx >> 10;
        int rr = idx & 1023;
        int hh = rr >> 1;
        int gg = (rr & 1) + 1;
        g_bias[idx] = b1[ll*3*HS + gg*HS + hh] + b2[ll*3*HS + gg*HS + hh];
    }
}

// ---------------------------------------------------------------------------
// Round x to tf32 once (8,388,608 float4)
// ---------------------------------------------------------------------------
__global__ void roundx_kernel(const float* __restrict__ x)
{
    int i4 = blockIdx.x * blockDim.x + threadIdx.x;
    float4 v = ((const float4*)x)[i4];
    v.x = rna_tf32(v.x); v.y = rna_tf32(v.y);
    v.z = rna_tf32(v.z); v.w = rna_tf32(v.w);
    ((float4*)g_xr)[i4] = v;
}

// ---------------------------------------------------------------------------
// Init: h0 (L,B,HS) -> Hbuf[0][l][h][b]; reset grid-barrier counter
// ---------------------------------------------------------------------------
__global__ void init_h_kernel(const float* __restrict__ h0)
{
    int idx = blockIdx.x * blockDim.x + threadIdx.x;   // 65536 threads
    if (idx == 0) g_arrive = 0ULL;
    int l = idx >> 15;
    int rem = idx & 32767;
    int b = rem >> 9;
    int h = rem & 511;
    g_Hbuf[(l*HS + h)*BB + b] = h0[idx];
}

// ---------------------------------------------------------------------------
// Kernel B: tf32 mma GEMM.  Gx[t][l][b][r] = sum_i x[b][t][i] * WG[l][r][i]
//   A = x tile (m=b=64, k), B = WG (k, n=r tile 128). grid (1024, 8, 2).
//   8 warps: (wid&3) = m-tile of 16, (wid>>2) = 64-wide r half (8 n8-tiles).
// ---------------------------------------------------------------------------
__global__ void __launch_bounds__(256) gemm_x_kernel()
{
    const int t  = blockIdx.x;
    const int rb = blockIdx.y * 128;
    const int l  = blockIdx.z;

    __shared__ __align__(16) float As[64*36];    // x tile [b][k], pitch 36
    __shared__ __align__(16) float Bs[128*36];   // W tile [r][k], pitch 36

    const int tid  = threadIdx.x;
    const int wid  = tid >> 5;
    const int lane = tid & 31;
    const int g    = lane >> 2;      // groupID
    const int tq   = lane & 3;       // threadID in group
    const int m0   = (wid & 3) * 16;
    const int nb0  = (wid >> 2) * 64;

    const float* xa = g_xr + (size_t)t * INW;                 // + b*SS*INW + k
    const float* wb = g_WG + ((size_t)l*ROWS + rb) * INW;     // + r*INW + k

    float acc[8][4];
    #pragma unroll
    for (int nt = 0; nt < 8; ++nt)
        #pragma unroll
        for (int j = 0; j < 4; ++j) acc[nt][j] = 0.0f;

    for (int k0 = 0; k0 < INW; k0 += 32) {
        __syncthreads();
        #pragma unroll
        for (int q = 0; q < 2; ++q) {              // As: 64 x 32 (512 f4)
            int i4 = tid + q*256;
            int b  = i4 >> 3, k4 = i4 & 7;
            float4 v = *(const float4*)(xa + (size_t)b*SS*INW + k0 + k4*4);
            *(float4*)&As[b*36 + k4*4] = v;
        }
        #pragma unroll
        for (int q = 0; q < 4; ++q) {              // Bs: 128 x 32 (1024 f4)
            int i4 = tid + q*256;
            int r  = i4 >> 3, k4 = i4 & 7;
            float4 v = *(const float4*)(wb + (size_t)r*INW + k0 + k4*4);
            *(float4*)&Bs[r*36 + k4*4] = v;
        }
        __syncthreads();
        #pragma unroll
        for (int ks = 0; ks < 4; ++ks) {
            int kk = ks*8;
            uint32_t a[4];
            a[0] = __float_as_uint(As[(m0+g  )*36 + kk + tq    ]);
            a[1] = __float_as_uint(As[(m0+g+8)*36 + kk + tq    ]);
            a[2] = __float_as_uint(As[(m0+g  )*36 + kk + tq + 4]);
            a[3] = __float_as_uint(As[(m0+g+8)*36 + kk + tq + 4]);
            #pragma unroll
            for (int nt = 0; nt < 8; ++nt) {
                int nrow = nb0 + nt*8 + g;
                uint32_t bf[2];
                bf[0] = __float_as_uint(Bs[nrow*36 + kk + tq    ]);
                bf[1] = __float_as_uint(Bs[nrow*36 + kk + tq + 4]);
                mma_tf32(acc[nt], a, bf);
            }
        }
    }

    float* gout = g_Gx + ((size_t)(t*L_NUM + l)*BB) * ROWS + rb;
    #pragma unroll
    for (int nt = 0; nt < 8; ++nt) {
        int r = nb0 + nt*8 + 2*tq;
        *(float2*)&gout[(size_t)(m0+g  )*ROWS + r] = make_float2(acc[nt][0], acc[nt][1]);
        *(float2*)&gout[(size_t)(m0+g+8)*ROWS + r] = make_float2(acc[nt][2], acc[nt][3]);
    }
}

// ---------------------------------------------------------------------------
// Kernel C: persistent scan with tf32 mma recurrent GEMM.
//   CTA: l = bid>>6, rows r0 = (bid&63)*16 -> one m16 tile, k = o = 512.
//   8 warps, each owns one n8 batch-tile; acc covers full k (no reduction).
//   UG tile 16x512 resident in SMEM (pitch 516); H streamed in 32-o chunks
//   as Hs[o][b] pitch 68 (tf32-rounded at stage time).
// ---------------------------------------------------------------------------
__global__ void __launch_bounds__(256, 1) step_kernel(float* __restrict__ out)
{
    const int tid  = threadIdx.x;
    const int lane = tid & 31;
    const int wid  = tid >> 5;
    const int g    = lane >> 2;
    const int tq   = lane & 3;
    const int l    = blockIdx.x >> 6;
    const int r0   = (blockIdx.x & 63) * 16;
    const int h0   = r0 >> 1;
    const int nb   = wid * 8;                     // warp's batch base

    __shared__ __align__(16) float UGs [16*516];  // 33.0 KB
    __shared__ __align__(16) float Hs  [32*68];   //  8.5 KB
    __shared__ __align__(16) float Dred[16*68];   //  4.3 KB

    {   // stage UG rows [16][512] -> pitch 516
        const float* src = g_UG + ((size_t)l*ROWS + r0)*HS;
        #pragma unroll
        for (int q = 0; q < 8; ++q) {
            int i4  = tid + q*256;                // 2048 f4
            int row = i4 >> 7;
            int c4  = i4 & 127;
            float4 v = *(const float4*)(src + (size_t)row*HS + c4*4);
            *(float4*)&UGs[row*516 + c4*4] = v;
        }
    }
    const float bz0 = g_bias[l*ROWS + r0 + 2*(tid&7)    ];
    const float bn0 = g_bias[l*ROWS + r0 + 2*(tid&7) + 1];

    float* outSeq   = out;
    float* outState = out + (size_t)SEQ_ELEMS;

    int p = 0;
    for (int t = 0; t < SS; ++t) {
        const float* Hrd = g_Hbuf + (size_t)(p*L_NUM + l)*HS*BB;
        float*       Hwr = g_Hbuf + (size_t)((1-p)*L_NUM + l)*HS*BB;

        float acc0[4] = {0,0,0,0};
        float acc1[4] = {0,0,0,0};

        for (int c = 0; c < 16; ++c) {
            __syncthreads();                       // Hs free
            #pragma unroll
            for (int q = 0; q < 2; ++q) {          // 32 o x 64 b chunk
                int i4 = tid + q*256;
                int o  = i4 >> 4, b4 = i4 & 15;
                float4 v = __ldcg((const float4*)(Hrd + (size_t)(c*32 + o)*BB + b4*4));
                v.x = rna_tf32(v.x); v.y = rna_tf32(v.y);
                v.z = rna_tf32(v.z); v.w = rna_tf32(v.w);
                *(float4*)&Hs[o*68 + b4*4] = v;
            }
            __syncthreads();
            #pragma unroll
            for (int ks = 0; ks < 4; ++ks) {
                int ko = c*32 + ks*8;              // global o
                int kk = ks*8;                     // local o
                uint32_t a[4], bf[2];
                a[0] = __float_as_uint(UGs[(g  )*516 + ko + tq    ]);
                a[1] = __float_as_uint(UGs[(g+8)*516 + ko + tq    ]);
                a[2] = __float_as_uint(UGs[(g  )*516 + ko + tq + 4]);
                a[3] = __float_as_uint(UGs[(g+8)*516 + ko + tq + 4]);
                bf[0] = __float_as_uint(Hs[(kk + tq    )*68 + nb + g]);
                bf[1] = __float_as_uint(Hs[(kk + tq + 4)*68 + nb + g]);
                if (ks & 1) mma_tf32(acc1, a, bf);
                else        mma_tf32(acc0, a, bf);
            }
        }

        // D frag -> Dred[16][68]
        *(float2*)&Dred[(g  )*68 + nb + 2*tq] = make_float2(acc0[0]+acc1[0], acc0[1]+acc1[1]);
        *(float2*)&Dred[(g+8)*68 + nb + 2*tq] = make_float2(acc0[2]+acc1[2], acc0[3]+acc1[3]);
        __syncthreads();

        const float* gx = g_Gx + ((size_t)(t*L_NUM + l)*BB)*ROWS + r0;
        #pragma unroll
        for (int it = 0; it < 2; ++it) {
            int u  = tid + it*256;                 // 512 (hh,b) updates
            int hh = u & 7;
            int b  = u >> 3;
            float2 gxv = *(const float2*)&gx[(size_t)b*ROWS + 2*hh];
            float gz = Dred[(2*hh  )*68 + b] + gxv.x + bz0;
            float gn = Dred[(2*hh+1)*68 + b] + gxv.y + bn0;
            float hold = __ldcg(&Hrd[(h0+hh)*BB + b]);
            float z = 1.0f / (1.0f + __expf(-gz));
            float n = tanhf(gn);
            float hnew = (1.0f - z)*n + z*hold;
            Hwr[(h0+hh)*BB + b] = hnew;
            if (l == 1)
                outSeq[((size_t)b*SS + t)*HS + h0 + hh] = hnew;
            if (t == SS-1)
                outState[((size_t)l*BB + b)*HS + h0 + hh] = hnew;
        }

        // grid barrier (monotonic counter; reset by init kernel each launch)
        __threadfence();
        __syncthreads();
        if (tid == 0) {
            atomicAdd(&g_arrive, 1ULL);
            unsigned long long target = (unsigned long long)(t+1) * NCTA;
            unsigned long long v;
            do {
                asm volatile("ld.global.acquire.gpu.u64 %0, [%1];"
                             : "=l"(v) : "l"(&g_arrive) : "memory");
            } while (v < target);
        }
        __syncthreads();
        p ^= 1;
    }
}

// ---------------------------------------------------------------------------
// Launch
// ---------------------------------------------------------------------------
extern "C" void kernel_launch(void* const* d_in, const int* in_sizes, int n_in,
                              void* d_out, int out_size)
{
    const float* x   = (const float*)d_in[0];
    const float* h0  = (const float*)d_in[1];
    const float* W1  = (const float*)d_in[2];
    const float* W2  = (const float*)d_in[3];
    const float* U1  = (const float*)d_in[4];
    const float* U2  = (const float*)d_in[5];
    const float* dW1 = (const float*)d_in[6];
    const float* dW2 = (const float*)d_in[7];
    const float* dU1 = (const float*)d_in[8];
    const float* dU2 = (const float*)d_in[9];
    const float* b1  = (const float*)d_in[10];
    const float* b2  = (const float*)d_in[11];
    float* out = (float*)d_out;

    combine_kernel<<<4096, 256>>>(W1, W2, U1, U2, dW1, dW2, dU1, dU2, b1, b2);
    roundx_kernel<<<32768, 256>>>(x);
    init_h_kernel<<<256, 256>>>(h0);
    dim3 gg(1024, 8, 2);
    gemm_x_kernel<<<gg, 256>>>();
    step_kernel<<<NCTA, 256>>>(out);
    (void)in_sizes; (void)n_in; (void)out_size;
}

// round 9
// speedup vs baseline: 2.8807x; 2.8807x over previous
#include <cuda_runtime.h>
#include <cstdint>

// ---------------------------------------------------------------------------
// Problem constants
// ---------------------------------------------------------------------------
#define L_NUM 2
#define HS    512
#define BB    64
#define SS    1024
#define INW   512
#define ROWS  1024            // 2 gates * HS, interleaved: r = 2*h + g' (g': 0=z, 1=n)
#define SEQ_ELEMS (BB*SS*HS)

// Scan partition: 2 layers x 4 batch-groups (16 b) x 16 row-groups (64 rows = 32 h)
#define NBG   4
#define NRG   16
#define GSIZE 16              // CTAs per barrier group (row-groups)

// ---------------------------------------------------------------------------
// Device scratch
// ---------------------------------------------------------------------------
__device__ __align__(16) float g_WG  [L_NUM*ROWS*INW];             // [l][r][i] tf32-rounded
__device__ __align__(16) float g_UG  [L_NUM*ROWS*HS];              // [l][r][o] tf32-rounded
__device__ __align__(16) float g_bias[L_NUM*ROWS];
__device__ __align__(16) float g_Gx  [(size_t)SS*L_NUM*BB*ROWS];   // 512 MB [t][l][b][r]
__device__ __align__(16) float g_Hbuf[2*L_NUM*BB*HS];              // ping-pong [p][l][b][o]
__device__ unsigned long long g_arrive[8*16];                      // 8 group counters, 128B apart

__device__ __forceinline__ float rna_tf32(float x) {
    uint32_t r;
    asm("cvt.rna.tf32.f32 %0, %1;" : "=r"(r) : "f"(x));
    return __uint_as_float(r);
}

// D (4xf32) += A (m16k8 tf32, row-major) * B (k8n8 tf32, col-major)
__device__ __forceinline__ void mma_tf32(float* d, const uint32_t* a, const uint32_t* bf) {
    asm volatile(
        "mma.sync.aligned.m16n8k8.row.col.f32.tf32.tf32.f32 "
        "{%0,%1,%2,%3}, {%4,%5,%6,%7}, {%8,%9}, {%0,%1,%2,%3};"
        : "+f"(d[0]), "+f"(d[1]), "+f"(d[2]), "+f"(d[3])
        : "r"(a[0]), "r"(a[1]), "r"(a[2]), "r"(a[3]), "r"(bf[0]), "r"(bf[1]));
}

// ---------------------------------------------------------------------------
// Kernel A: combined weights (tf32-rounded) + biases
// ---------------------------------------------------------------------------
__global__ void combine_kernel(const float* __restrict__ W1, const float* __restrict__ W2,
                               const float* __restrict__ U1, const float* __restrict__ U2,
                               const float* __restrict__ dW1, const float* __restrict__ dW2,
                               const float* __restrict__ dU1, const float* __restrict__ dU2,
                               const float* __restrict__ b1, const float* __restrict__ b2)
{
    int idx = blockIdx.x * blockDim.x + threadIdx.x;   // L*ROWS*INW threads
    int l   = idx >> 19;
    int rem = idx & 524287;
    int r   = rem >> 9;
    int i   = rem & 511;
    int h   = r >> 1;
    int g   = (r & 1) + 1;                             // original gate (1=z, 2=n)

    float w1  = W1 [l*3 + g];
    float dw1 = dW1[l*3 + g];
    float u1  = U1 [l*3 + g];
    float du1 = dU1[l*3 + g];
    int src = (l*HS + h)*INW + i;
    g_WG[idx] = rna_tf32(w1*W2[src] + dw1*dW2[src]);
    g_UG[idx] = rna_tf32(u1*U2[src] + du1*dU2[src]);

    if (idx < L_NUM*ROWS) {
        int ll = idx >> 10;
        int rr = idx & 1023;
        int hh = rr >> 1;
        int gg = (rr & 1) + 1;
        g_bias[idx] = b1[ll*3*HS + gg*HS + hh] + b2[ll*3*HS + gg*HS + hh];
    }
}

// ---------------------------------------------------------------------------
// Init: h0 (L,B,HS) -> Hbuf[0][l][b][h] (identical layout); reset barrier ctrs
// ---------------------------------------------------------------------------
__global__ void init_h_kernel(const float* __restrict__ h0)
{
    int idx = blockIdx.x * blockDim.x + threadIdx.x;   // 65536 threads
    if (idx < 8*16) g_arrive[idx] = 0ULL;
    g_Hbuf[idx] = h0[idx];
}

// ---------------------------------------------------------------------------
// Kernel B: tf32 mma GEMM.  Gx[t][l][b][r] = sum_i x[b][t][i] * WG[l][r][i]
//   grid (1024, 8, 2); 8 warps: (wid&3)=m16 b-tile, (wid>>2)=64-wide r half.
//   x rounded to tf32 inline at the SMEM stage (no separate pass).
// ---------------------------------------------------------------------------
__global__ void __launch_bounds__(256) gemm_x_kernel(const float* __restrict__ x)
{
    const int t  = blockIdx.x;
    const int rb = blockIdx.y * 128;
    const int l  = blockIdx.z;

    __shared__ __align__(16) float As[64*36];    // x tile [b][k], pitch 36
    __shared__ __align__(16) float Bs[128*36];   // W tile [r][k], pitch 36

    const int tid  = threadIdx.x;
    const int wid  = tid >> 5;
    const int lane = tid & 31;
    const int g    = lane >> 2;
    const int tq   = lane & 3;
    const int m0   = (wid & 3) * 16;
    const int nb0  = (wid >> 2) * 64;

    const float* xa = x + (size_t)t * INW;                    // + b*SS*INW + k
    const float* wb = g_WG + ((size_t)l*ROWS + rb) * INW;     // + r*INW + k

    float acc[8][4];
    #pragma unroll
    for (int nt = 0; nt < 8; ++nt)
        #pragma unroll
        for (int j = 0; j < 4; ++j) acc[nt][j] = 0.0f;

    for (int k0 = 0; k0 < INW; k0 += 32) {
        __syncthreads();
        #pragma unroll
        for (int q = 0; q < 2; ++q) {              // As: 64 x 32
            int i4 = tid + q*256;
            int b  = i4 >> 3, k4 = i4 & 7;
            float4 v = *(const float4*)(xa + (size_t)b*SS*INW + k0 + k4*4);
            v.x = rna_tf32(v.x); v.y = rna_tf32(v.y);
            v.z = rna_tf32(v.z); v.w = rna_tf32(v.w);
            *(float4*)&As[b*36 + k4*4] = v;
        }
        #pragma unroll
        for (int q = 0; q < 4; ++q) {              // Bs: 128 x 32
            int i4 = tid + q*256;
            int r  = i4 >> 3, k4 = i4 & 7;
            float4 v = *(const float4*)(wb + (size_t)r*INW + k0 + k4*4);
            *(float4*)&Bs[r*36 + k4*4] = v;
        }
        __syncthreads();
        #pragma unroll
        for (int ksi = 0; ksi < 4; ++ksi) {
            int kk = ksi*8;
            uint32_t a[4];
            a[0] = __float_as_uint(As[(m0+g  )*36 + kk + tq    ]);
            a[1] = __float_as_uint(As[(m0+g+8)*36 + kk + tq    ]);
            a[2] = __float_as_uint(As[(m0+g  )*36 + kk + tq + 4]);
            a[3] = __float_as_uint(As[(m0+g+8)*36 + kk + tq + 4]);
            #pragma unroll
            for (int nt = 0; nt < 8; ++nt) {
                int nrow = nb0 + nt*8 + g;
                uint32_t bf[2];
                bf[0] = __float_as_uint(Bs[nrow*36 + kk + tq    ]);
                bf[1] = __float_as_uint(Bs[nrow*36 + kk + tq + 4]);
                mma_tf32(acc[nt], a, bf);
            }
        }
    }

    float* gout = g_Gx + ((size_t)(t*L_NUM + l)*BB) * ROWS + rb;
    #pragma unroll
    for (int nt = 0; nt < 8; ++nt) {
        int r = nb0 + nt*8 + 2*tq;
        *(float2*)&gout[(size_t)(m0+g  )*ROWS + r] = make_float2(acc[nt][0], acc[nt][1]);
        *(float2*)&gout[(size_t)(m0+g+8)*ROWS + r] = make_float2(acc[nt][2], acc[nt][3]);
    }
}

// ---------------------------------------------------------------------------
// Kernel C: persistent scan, batch-group partition.
//   CTA (l, bg, j): 16 batches (bg), 64 rows (j)  ->  m16(b) x n64(r) x k512.
//   512 thr = 16 warps: (wid&1)=k half (256), (wid>>1)=n8 row tile.
//   UG B-frags hoisted to 64 regs/thread for the whole kernel.
//   Per step: stage H slice (16x512) coalesced -> 32x(4 LDS + HMMA)/warp ->
//   Dred -> fused update. Barrier: per-(l,bg) 16-CTA counter.
// ---------------------------------------------------------------------------
__global__ void __launch_bounds__(512, 1) step_kernel(float* __restrict__ out)
{
    const int tid  = threadIdx.x;
    const int lane = tid & 31;
    const int wid  = tid >> 5;
    const int g    = lane >> 2;
    const int tq   = lane & 3;

    const int bid  = blockIdx.x;
    const int l    = bid >> 6;
    const int bg   = (bid >> 4) & 3;
    const int j    = bid & 15;
    const int gid  = l*NBG + bg;
    const int rbase = j * 64;
    const int hbase = j * 32;

    const int ks    = wid & 1;          // k half
    const int nt    = wid >> 1;         // n8 tile (0..7)
    const int kbase = ks * 256;
    const int rW    = rbase + nt*8;     // warp's 8 rows

    __shared__ __align__(16) float Hs  [16*516];     // 33.0 KB  [bl][o]
    __shared__ __align__(16) float Dred[2*16*66];    //  8.4 KB  [ks][bl][r64]

    // --- hoist UG B-frags into registers (static all kernel) ---
    uint32_t breg[32][2];
    {
        const float* ug = g_UG + ((size_t)l*ROWS + rW + g)*HS + kbase;
        #pragma unroll
        for (int m = 0; m < 32; ++m) {
            breg[m][0] = __float_as_uint(ug[m*8 + tq    ]);
            breg[m][1] = __float_as_uint(ug[m*8 + tq + 4]);
        }
    }

    // update-phase identity: one (h, b) pair per thread
    const int hh = tid & 31;            // local h (0..31)
    const int bl = tid >> 5;            // local b (0..15)
    const int bglob = bg*16 + bl;
    const float bz = g_bias[l*ROWS + rbase + 2*hh];
    const float bn = g_bias[l*ROWS + rbase + 2*hh + 1];

    float* outSeq   = out;
    float* outState = out + (size_t)SEQ_ELEMS;
    unsigned long long* bar = &g_arrive[gid*16];

    int p = 0;
    for (int t = 0; t < SS; ++t) {
        const float* Hrd = g_Hbuf + (size_t)(p*L_NUM + l)*BB*HS;       // [b][o]
        float*       Hwr = g_Hbuf + (size_t)((1-p)*L_NUM + l)*BB*HS;

        // --- prefetch gx (DRAM stream) + hold (L2) for the update phase ---
        const float2 gxv = __ldcs((const float2*)&g_Gx[
            ((size_t)(t*L_NUM + l)*BB + bglob)*ROWS + rbase + 2*hh]);
        const float hold = __ldcg(&Hrd[(size_t)bglob*HS + hbase + hh]);

        // --- stage H slice: 16 b-rows x 512 o, tf32-rounded, pitch 516 ---
        #pragma unroll
        for (int q = 0; q < 4; ++q) {
            int i4   = tid + q*512;               // 2048 float4
            int row  = i4 >> 7;
            int col4 = i4 & 127;
            float4 v = __ldcg((const float4*)(Hrd + (size_t)(bg*16 + row)*HS + col4*4));
            v.x = rna_tf32(v.x); v.y = rna_tf32(v.y);
            v.z = rna_tf32(v.z); v.w = rna_tf32(v.w);
            *(float4*)&Hs[row*516 + col4*4] = v;
        }
        __syncthreads();

        // --- mma: m16(b) x n8(r) x k256 per warp ---
        float acc0[4] = {0,0,0,0};
        float acc1[4] = {0,0,0,0};
        #pragma unroll
        for (int m = 0; m < 32; ++m) {
            int ko = kbase + m*8;
            uint32_t a[4];
            a[0] = __float_as_uint(Hs[(g  )*516 + ko + tq    ]);
            a[1] = __float_as_uint(Hs[(g+8)*516 + ko + tq    ]);
            a[2] = __float_as_uint(Hs[(g  )*516 + ko + tq + 4]);
            a[3] = __float_as_uint(Hs[(g+8)*516 + ko + tq + 4]);
            if (m & 1) mma_tf32(acc1, a, breg[m]);
            else       mma_tf32(acc0, a, breg[m]);
        }
        // C[m=b][n=r]: c0=C[g][2tq], c1=C[g][2tq+1], c2=C[g+8][2tq], c3=...
        {
            float* dr = &Dred[(ks*16 + g)*66 + nt*8 + 2*tq];
            *(float2*)dr          = make_float2(acc0[0]+acc1[0], acc0[1]+acc1[1]);
            *(float2*)(dr + 8*66) = make_float2(acc0[2]+acc1[2], acc0[3]+acc1[3]);
        }
        __syncthreads();

        // --- fused update: one (hh, bl) per thread ---
        {
            float2 d0 = *(const float2*)&Dred[(     bl)*66 + 2*hh];
            float2 d1 = *(const float2*)&Dred[(16 + bl)*66 + 2*hh];
            float gz = d0.x + d1.x + gxv.x + bz;
            float gn = d0.y + d1.y + gxv.y + bn;
            float z = 1.0f / (1.0f + __expf(-gz));
            float n = tanhf(gn);
            float hnew = (1.0f - z)*n + z*hold;
            Hwr[(size_t)bglob*HS + hbase + hh] = hnew;
            if (l == 1)
                outSeq[((size_t)bglob*SS + t)*HS + hbase + hh] = hnew;
            if (t == SS-1)
                outState[((size_t)l*BB + bglob)*HS + hbase + hh] = hnew;
        }

        // --- per-group 16-CTA barrier (monotonic counter) ---
        __threadfence();
        __syncthreads();
        if (tid == 0) {
            atomicAdd(bar, 1ULL);
            unsigned long long target = (unsigned long long)(t+1) * GSIZE;
            unsigned long long v;
            do {
                asm volatile("ld.global.acquire.gpu.u64 %0, [%1];"
                             : "=l"(v) : "l"(bar) : "memory");
            } while (v < target);
        }
        __syncthreads();
        p ^= 1;
    }
}

// ---------------------------------------------------------------------------
// Launch
// ---------------------------------------------------------------------------
extern "C" void kernel_launch(void* const* d_in, const int* in_sizes, int n_in,
                              void* d_out, int out_size)
{
    const float* x   = (const float*)d_in[0];
    const float* h0  = (const float*)d_in[1];
    const float* W1  = (const float*)d_in[2];
    const float* W2  = (const float*)d_in[3];
    const float* U1  = (const float*)d_in[4];
    const float* U2  = (const float*)d_in[5];
    const float* dW1 = (const float*)d_in[6];
    const float* dW2 = (const float*)d_in[7];
    const float* dU1 = (const float*)d_in[8];
    const float* dU2 = (const float*)d_in[9];
    const float* b1  = (const float*)d_in[10];
    const float* b2  = (const float*)d_in[11];
    float* out = (float*)d_out;

    combine_kernel<<<4096, 256>>>(W1, W2, U1, U2, dW1, dW2, dU1, dU2, b1, b2);
    init_h_kernel<<<256, 256>>>(h0);
    dim3 gg(1024, 8, 2);
    gemm_x_kernel<<<gg, 256>>>(x);
    step_kernel<<<128, 512>>>(out);
    (void)in_sizes; (void)n_in; (void)out_size;
}